// round 1
// baseline (speedup 1.0000x reference)
#include <cuda_runtime.h>
#include <cstdint>

#define Bn 32
#define Cn 64
#define Hn 64
#define Wn 64
#define In 128
#define TAPS 9
#define CCn 8
#define TILE 16

// Scratch (no allocations allowed): combined weights in [c][tap][i] layout + bias.
__device__ float g_w2[Cn * TAPS * In];   // 2*|w|*t
__device__ float g_wn[Cn * TAPS * In];   // -|w|
__device__ float g_nt3[In];              // -sum(|w|*t^2)

__global__ void prep_weights(const float* __restrict__ tp, const float* __restrict__ sw) {
    int idx = blockIdx.x * blockDim.x + threadIdx.x;
    if (idx >= In * Cn * TAPS) return;
    int i   = idx / (Cn * TAPS);
    int rem = idx - i * (Cn * TAPS);
    int c   = rem / TAPS;
    int tap = rem - c * TAPS;
    float w = fabsf(sw[idx]);
    float t = tp[idx];
    int o = (c * TAPS + tap) * In + i;
    g_w2[o] = 2.0f * w * t;
    g_wn[o] = -w;
}

__global__ void prep_t3(const float* __restrict__ tp, const float* __restrict__ sw) {
    int i = blockIdx.x;
    int c = threadIdx.x;  // 64 threads == Cn
    float s = 0.f;
    int base = (i * Cn + c) * TAPS;
#pragma unroll
    for (int tap = 0; tap < TAPS; tap++) {
        float w = fabsf(sw[base + tap]);
        float t = tp[base + tap];
        s += w * t * t;
    }
    __shared__ float red[64];
    red[c] = s;
    __syncthreads();
    for (int off = 32; off > 0; off >>= 1) {
        if (c < off) red[c] += red[c + off];
        __syncthreads();
    }
    if (c == 0) g_nt3[i] = -red[0];
}

__device__ __forceinline__ uint64_t pack2(float v) {
    uint64_t r;
    asm("mov.b64 %0, {%1, %2};" : "=l"(r) : "f"(v), "f"(v));
    return r;
}
__device__ __forceinline__ uint64_t ffma2(uint64_t a, uint64_t b, uint64_t c) {
    uint64_t d;
    asm("fma.rn.f32x2 %0, %1, %2, %3;" : "=l"(d) : "l"(a), "l"(b), "l"(c));
    return d;
}
__device__ __forceinline__ void unpack2(uint64_t v, float& lo, float& hi) {
    asm("mov.b64 {%0, %1}, %2;" : "=f"(lo), "=f"(hi) : "l"(v));
}

// Block: one batch b, one 16x16 spatial tile, 32 instances.
// 256 threads = 4 instance-groups (8 instances each, as 4 f32x2 pairs)
//             x 64 position-threads (4 rows strided by 4, same column).
__global__ __launch_bounds__(256) void sim_kernel(const float* __restrict__ x,
                                                  float* __restrict__ out) {
    __shared__ __align__(16) float sx[CCn * 18 * 18];
    __shared__ __align__(16) float sw2s[CCn * TAPS * 32];
    __shared__ __align__(16) float swns[CCn * TAPS * 32];

    const int tid = threadIdx.x;
    const int ig  = tid >> 6;    // instance subgroup 0..3
    const int pt  = tid & 63;    // position thread
    const int px  = pt & 15;     // column in tile
    const int py0 = pt >> 4;     // base row 0..3 (rows py0 + 4p)

    const int bx     = blockIdx.x;        // 0..15 spatial tile
    const int b      = blockIdx.y;        // batch
    const int i_base = blockIdx.z * 32;   // instance block
    const int by0 = (bx >> 2) * TILE;
    const int bx0 = (bx & 3) * TILE;

    uint64_t acc[4][4];
#pragma unroll
    for (int p = 0; p < 4; p++)
#pragma unroll
        for (int m = 0; m < 4; m++) acc[p][m] = 0ULL;

    for (int c0 = 0; c0 < Cn; c0 += CCn) {
        __syncthreads();
        // Load x tile (18x18 halo) for CCn channels; zero pad out of bounds.
        for (int j = tid; j < CCn * 324; j += 256) {
            int cc  = j / 324;
            int r   = (j - cc * 324) / 18;
            int col = j - cc * 324 - r * 18;
            int gy = by0 + r - 1;
            int gx = bx0 + col - 1;
            float v = 0.f;
            if ((unsigned)gy < Hn && (unsigned)gx < Wn)
                v = x[((b * Cn + c0 + cc) * Hn + gy) * Wn + gx];
            sx[j] = v;
        }
        // Load weights for this channel chunk: [cc][tap][32 instances]
        for (int j = tid; j < CCn * TAPS * 32; j += 256) {
            int cc  = j / 288;
            int rem = j - cc * 288;
            int tap = rem >> 5;
            int il  = rem & 31;
            int g = ((c0 + cc) * TAPS + tap) * In + i_base + il;
            sw2s[j] = g_w2[g];
            swns[j] = g_wn[g];
        }
        __syncthreads();

#pragma unroll
        for (int cc = 0; cc < CCn; cc++) {
            const float* xb = &sx[cc * 324];
#pragma unroll
            for (int kh = 0; kh < 3; kh++) {
#pragma unroll
                for (int kw = 0; kw < 3; kw++) {
                    const int tap = kh * 3 + kw;
                    const uint64_t* p2 =
                        (const uint64_t*)(sw2s + (cc * TAPS + tap) * 32) + ig * 4;
                    const uint64_t* pn =
                        (const uint64_t*)(swns + (cc * TAPS + tap) * 32) + ig * 4;
                    uint64_t w2r[4], wnr[4];
#pragma unroll
                    for (int m = 0; m < 4; m++) { w2r[m] = p2[m]; wnr[m] = pn[m]; }
#pragma unroll
                    for (int p = 0; p < 4; p++) {
                        const int row = py0 + p * 4 + kh;
                        float xv = xb[row * 18 + px + kw];
                        uint64_t xp = pack2(xv);
#pragma unroll
                        for (int m = 0; m < 4; m++) {
                            // acc += xv * (w2 + wn*xv)  ==  2|w|t*x - |w|*x^2
                            uint64_t t = ffma2(wnr[m], xp, w2r[m]);
                            acc[p][m] = ffma2(xp, t, acc[p][m]);
                        }
                    }
                }
            }
        }
    }

    // Epilogue: add -t3[i] bias and store.
#pragma unroll
    for (int p = 0; p < 4; p++) {
        const int gy = by0 + py0 + p * 4;
        const int gx = bx0 + px;
#pragma unroll
        for (int m = 0; m < 4; m++) {
            float lo, hi;
            unpack2(acc[p][m], lo, hi);
            const int i0 = i_base + ig * 8 + 2 * m;
            out[((b * In + i0) * Hn + gy) * Wn + gx]     = lo + g_nt3[i0];
            out[((b * In + i0 + 1) * Hn + gy) * Wn + gx] = hi + g_nt3[i0 + 1];
        }
    }
}

extern "C" void kernel_launch(void* const* d_in, const int* in_sizes, int n_in,
                              void* d_out, int out_size) {
    const float* x  = (const float*)d_in[0];
    const float* tp = (const float*)d_in[1];
    const float* sw = (const float*)d_in[2];
    float* out = (float*)d_out;

    prep_weights<<<(In * Cn * TAPS + 255) / 256, 256>>>(tp, sw);
    prep_t3<<<In, 64>>>(tp, sw);

    dim3 grid(16, Bn, In / 32);
    sim_kernel<<<grid, 256>>>(x, out);
}

// round 2
// speedup vs baseline: 1.0000x; 1.0000x over previous
#include <cuda_runtime.h>
#include <cstdint>

#define Bn 32
#define Cn 64
#define Hn 64
#define Wn 64
#define In 128
#define TAPS 9
#define CCn 8
#define TILE 16

// Scratch (no allocations allowed): combined weights in [c][tap][i] layout + bias.
__device__ float g_w2[Cn * TAPS * In];   // 2*|w|*t
__device__ float g_wn[Cn * TAPS * In];   // -|w|
__device__ float g_nt3[In];              // -sum(|w|*t^2)

__global__ void prep_weights(const float* __restrict__ tp, const float* __restrict__ sw) {
    int idx = blockIdx.x * blockDim.x + threadIdx.x;
    if (idx >= In * Cn * TAPS) return;
    int i   = idx / (Cn * TAPS);
    int rem = idx - i * (Cn * TAPS);
    int c   = rem / TAPS;
    int tap = rem - c * TAPS;
    float w = fabsf(sw[idx]);
    float t = tp[idx];
    int o = (c * TAPS + tap) * In + i;
    g_w2[o] = 2.0f * w * t;
    g_wn[o] = -w;
}

__global__ void prep_t3(const float* __restrict__ tp, const float* __restrict__ sw) {
    int i = blockIdx.x;
    int c = threadIdx.x;  // 64 threads == Cn
    float s = 0.f;
    int base = (i * Cn + c) * TAPS;
#pragma unroll
    for (int tap = 0; tap < TAPS; tap++) {
        float w = fabsf(sw[base + tap]);
        float t = tp[base + tap];
        s += w * t * t;
    }
    __shared__ float red[64];
    red[c] = s;
    __syncthreads();
    for (int off = 32; off > 0; off >>= 1) {
        if (c < off) red[c] += red[c + off];
        __syncthreads();
    }
    if (c == 0) g_nt3[i] = -red[0];
}

__device__ __forceinline__ uint64_t pack2(float v) {
    uint64_t r;
    asm("mov.b64 %0, {%1, %2};" : "=l"(r) : "f"(v), "f"(v));
    return r;
}
__device__ __forceinline__ uint64_t ffma2(uint64_t a, uint64_t b, uint64_t c) {
    uint64_t d;
    asm("fma.rn.f32x2 %0, %1, %2, %3;" : "=l"(d) : "l"(a), "l"(b), "l"(c));
    return d;
}
__device__ __forceinline__ void unpack2(uint64_t v, float& lo, float& hi) {
    asm("mov.b64 {%0, %1}, %2;" : "=f"(lo), "=f"(hi) : "l"(v));
}

// Block: one batch b, one 16x16 spatial tile, 32 instances.
// 256 threads = 4 instance-groups (8 instances each, as 4 f32x2 pairs)
//             x 64 position-threads (4 rows strided by 4, same column).
__global__ __launch_bounds__(256) void sim_kernel(const float* __restrict__ x,
                                                  float* __restrict__ out) {
    __shared__ __align__(16) float sx[CCn * 18 * 18];
    __shared__ __align__(16) float sw2s[CCn * TAPS * 32];
    __shared__ __align__(16) float swns[CCn * TAPS * 32];

    const int tid = threadIdx.x;
    const int ig  = tid >> 6;    // instance subgroup 0..3
    const int pt  = tid & 63;    // position thread
    const int px  = pt & 15;     // column in tile
    const int py0 = pt >> 4;     // base row 0..3 (rows py0 + 4p)

    const int bx     = blockIdx.x;        // 0..15 spatial tile
    const int b      = blockIdx.y;        // batch
    const int i_base = blockIdx.z * 32;   // instance block
    const int by0 = (bx >> 2) * TILE;
    const int bx0 = (bx & 3) * TILE;

    uint64_t acc[4][4];
#pragma unroll
    for (int p = 0; p < 4; p++)
#pragma unroll
        for (int m = 0; m < 4; m++) acc[p][m] = 0ULL;

    for (int c0 = 0; c0 < Cn; c0 += CCn) {
        __syncthreads();
        // Load x tile (18x18 halo) for CCn channels; zero pad out of bounds.
        for (int j = tid; j < CCn * 324; j += 256) {
            int cc  = j / 324;
            int r   = (j - cc * 324) / 18;
            int col = j - cc * 324 - r * 18;
            int gy = by0 + r - 1;
            int gx = bx0 + col - 1;
            float v = 0.f;
            if ((unsigned)gy < Hn && (unsigned)gx < Wn)
                v = x[((b * Cn + c0 + cc) * Hn + gy) * Wn + gx];
            sx[j] = v;
        }
        // Load weights for this channel chunk: [cc][tap][32 instances]
        for (int j = tid; j < CCn * TAPS * 32; j += 256) {
            int cc  = j / 288;
            int rem = j - cc * 288;
            int tap = rem >> 5;
            int il  = rem & 31;
            int g = ((c0 + cc) * TAPS + tap) * In + i_base + il;
            sw2s[j] = g_w2[g];
            swns[j] = g_wn[g];
        }
        __syncthreads();

#pragma unroll
        for (int cc = 0; cc < CCn; cc++) {
            const float* xb = &sx[cc * 324];
#pragma unroll
            for (int kh = 0; kh < 3; kh++) {
#pragma unroll
                for (int kw = 0; kw < 3; kw++) {
                    const int tap = kh * 3 + kw;
                    const uint64_t* p2 =
                        (const uint64_t*)(sw2s + (cc * TAPS + tap) * 32) + ig * 4;
                    const uint64_t* pn =
                        (const uint64_t*)(swns + (cc * TAPS + tap) * 32) + ig * 4;
                    uint64_t w2r[4], wnr[4];
#pragma unroll
                    for (int m = 0; m < 4; m++) { w2r[m] = p2[m]; wnr[m] = pn[m]; }
#pragma unroll
                    for (int p = 0; p < 4; p++) {
                        const int row = py0 + p * 4 + kh;
                        float xv = xb[row * 18 + px + kw];
                        uint64_t xp = pack2(xv);
#pragma unroll
                        for (int m = 0; m < 4; m++) {
                            // acc += xv * (w2 + wn*xv)  ==  2|w|t*x - |w|*x^2
                            uint64_t t = ffma2(wnr[m], xp, w2r[m]);
                            acc[p][m] = ffma2(xp, t, acc[p][m]);
                        }
                    }
                }
            }
        }
    }

    // Epilogue: add -t3[i] bias and store.
#pragma unroll
    for (int p = 0; p < 4; p++) {
        const int gy = by0 + py0 + p * 4;
        const int gx = bx0 + px;
#pragma unroll
        for (int m = 0; m < 4; m++) {
            float lo, hi;
            unpack2(acc[p][m], lo, hi);
            const int i0 = i_base + ig * 8 + 2 * m;
            out[((b * In + i0) * Hn + gy) * Wn + gx]     = lo + g_nt3[i0];
            out[((b * In + i0 + 1) * Hn + gy) * Wn + gx] = hi + g_nt3[i0 + 1];
        }
    }
}

extern "C" void kernel_launch(void* const* d_in, const int* in_sizes, int n_in,
                              void* d_out, int out_size) {
    const float* x  = (const float*)d_in[0];
    const float* tp = (const float*)d_in[1];
    const float* sw = (const float*)d_in[2];
    float* out = (float*)d_out;

    prep_weights<<<(In * Cn * TAPS + 255) / 256, 256>>>(tp, sw);
    prep_t3<<<In, 64>>>(tp, sw);

    dim3 grid(16, Bn, In / 32);
    sim_kernel<<<grid, 256>>>(x, out);
}

// round 4
// speedup vs baseline: 3.6327x; 3.6325x over previous
#include <cuda_runtime.h>
#include <cuda_fp16.h>
#include <cstdint>

#define Bn 32
#define Cn 64
#define Hn 64
#define Wn 64
#define In 128
#define RT 3
#define WPAD 72
#define NPOS 192
#define BROWS 360
#define BSTRIDE 264            // bytes per B row: 64 half2 + 8B pad
#define ASTRIDE 48             // bytes per A row: 16 fp16 + 16B pad
#define ACHUNK (128 * ASTRIDE) // 6144
#define ATAP (8 * ACHUNK)      // 49152
#define SM_A 0
#define SM_B (2 * ATAP)        // 98304
#define SMEM_TOTAL (SM_B + BROWS * BSTRIDE) // 193344

__device__ __align__(16) unsigned char g_A[9 * ATAP]; // packed fp16 A, padded rows
__device__ float g_nt3[In];

// ---------------- prep: A[tap][chunk][row=i][16 fp16 @48B] ----------------
__global__ void prep_A(const float* __restrict__ tp, const float* __restrict__ sw) {
    int idx = blockIdx.x * 256 + threadIdx.x;
    if (idx >= 9 * 8 * 128 * 16) return;
    int e     = idx & 15;
    int row   = (idx >> 4) & 127;
    int chunk = (idx >> 11) & 7;
    int tap   = idx >> 14;
    int kk = chunk * 16 + e;        // global k within tap
    int c = kk >> 1, s = kk & 1;
    int kh = tap / 3, kw = tap - kh * 3;
    int widx = ((row * Cn + c) * 3 + kh) * 3 + kw;
    float w = fabsf(sw[widx]);
    float t = tp[widx];
    float val = s ? -w : 2.0f * w * t;   // s=0 pairs x, s=1 pairs x^2
    *(__half*)(g_A + (size_t)tap * ATAP + chunk * ACHUNK + row * ASTRIDE + e * 2) =
        __float2half_rn(val);
}

__global__ void prep_t3(const float* __restrict__ tp, const float* __restrict__ sw) {
    int i = blockIdx.x;
    int c = threadIdx.x;
    float s = 0.f;
    int base = (i * Cn + c) * 9;
#pragma unroll
    for (int tap = 0; tap < 9; tap++) {
        float w = fabsf(sw[base + tap]);
        float t = tp[base + tap];
        s += w * t * t;
    }
    __shared__ float red[64];
    red[c] = s;
    __syncthreads();
    for (int off = 32; off > 0; off >>= 1) {
        if (c < off) red[c] += red[c + off];
        __syncthreads();
    }
    if (c == 0) g_nt3[i] = -red[0];
}

// ---------------- helpers ----------------
__device__ __forceinline__ uint32_t lds32(const unsigned char* p) {
    return *(const uint32_t*)p;
}
__device__ __forceinline__ void mma16816(float* c, const uint32_t a0, const uint32_t a1,
                                         const uint32_t a2, const uint32_t a3,
                                         const uint32_t b0, const uint32_t b1) {
    asm volatile(
        "mma.sync.aligned.m16n8k16.row.col.f32.f16.f16.f32 "
        "{%0,%1,%2,%3}, {%4,%5,%6,%7}, {%8,%9}, {%0,%1,%2,%3};"
        : "+f"(c[0]), "+f"(c[1]), "+f"(c[2]), "+f"(c[3])
        : "r"(a0), "r"(a1), "r"(a2), "r"(a3), "r"(b0), "r"(b1));
}

// ---------------- main: grid (22 row-tiles, 32 batches), 256 threads ----------------
__global__ void __launch_bounds__(256, 1) sim_mma(const float* __restrict__ x,
                                                  float* __restrict__ out) {
    extern __shared__ __align__(16) unsigned char smem[];
    const int tid  = threadIdx.x;
    const int lane = tid & 31;
    const int warp = tid >> 5;
    const int wm = warp & 1;   // M half: instances [wm*64, wm*64+64)
    const int wn = warp >> 1;  // N quarter: positions [wn*48, wn*48+48)
    const int b  = blockIdx.y;
    const int y0 = blockIdx.x * RT;

    // ---- B fill: row r = li*72+lx holds 64 half2 (x, x^2) per channel ----
    const float* xb = x + (size_t)b * Cn * Hn * Wn;
    for (int idx = tid; idx < Cn * BROWS; idx += 256) {
        int c = idx / BROWS;
        int r = idx - c * BROWS;
        int li = r / WPAD;
        int lx = r - li * WPAD;
        int gy = y0 + li - 1, gx = lx - 1;
        float v = 0.f;
        if ((unsigned)gy < Hn && (unsigned)gx < Wn) v = xb[(c * Hn + gy) * Wn + gx];
        __half2 h = __floats2half2_rn(v, v * v);
        *(uint32_t*)(smem + SM_B + r * BSTRIDE + c * 4) = *(uint32_t*)&h;
    }

    // ---- per-lane fragment base addresses ----
    uint32_t bbase[6];
#pragma unroll
    for (int j = 0; j < 6; j++) {
        int p = wn * 48 + j * 8 + (lane >> 2);
        bbase[j] = SM_B + (uint32_t)(((p >> 6) * WPAD + (p & 63)) * BSTRIDE) + (lane & 3) * 4;
    }
    uint32_t arow[4];
#pragma unroll
    for (int t = 0; t < 4; t++)
        arow[t] = (uint32_t)((wm * 64 + t * 16 + (lane >> 2)) * ASTRIDE) + (lane & 3) * 4;

    float acc[4][6][4];
#pragma unroll
    for (int t = 0; t < 4; t++)
#pragma unroll
        for (int j = 0; j < 6; j++)
#pragma unroll
            for (int q = 0; q < 4; q++) acc[t][j][q] = 0.f;

    // ---- main loop: 9 taps x 8 k16-chunks ----
    for (int tap = 0; tap < 9; tap++) {
        // stage A for this tap (double-buffered by tap parity)
        {
            const float4* src = (const float4*)(g_A + (size_t)tap * ATAP);
            float4* dst = (float4*)(smem + SM_A + (tap & 1) * ATAP);
            for (int j = tid; j < ATAP / 16; j += 256) dst[j] = src[j];
        }
        __syncthreads();

        const int kh = tap / 3, kw = tap - kh * 3;
        const uint32_t tapoff = (uint32_t)((kh * WPAD + kw) * BSTRIDE);
        const uint32_t abuf = SM_A + (tap & 1) * ATAP;

#pragma unroll
        for (int chunk = 0; chunk < 8; chunk++) {
            uint32_t a[4][4];
#pragma unroll
            for (int t = 0; t < 4; t++) {
                const unsigned char* ad = smem + abuf + chunk * ACHUNK + arow[t];
                a[t][0] = lds32(ad);
                a[t][1] = lds32(ad + 8 * ASTRIDE);
                a[t][2] = lds32(ad + 16);
                a[t][3] = lds32(ad + 8 * ASTRIDE + 16);
            }
#pragma unroll
            for (int j = 0; j < 6; j++) {
                const unsigned char* bd = smem + bbase[j] + tapoff + chunk * 32;
                uint32_t b0 = lds32(bd);
                uint32_t b1 = lds32(bd + 16);
#pragma unroll
                for (int t = 0; t < 4; t++)
                    mma16816(acc[t][j], a[t][0], a[t][1], a[t][2], a[t][3], b0, b1);
            }
        }
        __syncthreads();
    }

    // ---- epilogue: bias + store float2 pairs ----
#pragma unroll
    for (int t = 0; t < 4; t++) {
        const int m_lo = wm * 64 + t * 16 + (lane >> 2);
        const int m_hi = m_lo + 8;
        const float bias_lo = g_nt3[m_lo];
        const float bias_hi = g_nt3[m_hi];
        float* o_lo = out + ((size_t)b * In + m_lo) * Hn * Wn;
        float* o_hi = out + ((size_t)b * In + m_hi) * Hn * Wn;
#pragma unroll
        for (int j = 0; j < 6; j++) {
            const int p = wn * 48 + j * 8 + 2 * (lane & 3);
            const int gy = y0 + (p >> 6);
            const int xc = p & 63;
            if (gy < Hn) {
                float2 v0 = make_float2(acc[t][j][0] + bias_lo, acc[t][j][1] + bias_lo);
                float2 v1 = make_float2(acc[t][j][2] + bias_hi, acc[t][j][3] + bias_hi);
                *(float2*)(o_lo + gy * Wn + xc) = v0;
                *(float2*)(o_hi + gy * Wn + xc) = v1;
            }
        }
    }
}

extern "C" void kernel_launch(void* const* d_in, const int* in_sizes, int n_in,
                              void* d_out, int out_size) {
    const float* x  = (const float*)d_in[0];
    const float* tp = (const float*)d_in[1];
    const float* sw = (const float*)d_in[2];
    float* out = (float*)d_out;

    cudaFuncSetAttribute(sim_mma, cudaFuncAttributeMaxDynamicSharedMemorySize, SMEM_TOTAL);

    prep_A<<<(9 * 8 * 128 * 16 + 255) / 256, 256>>>(tp, sw);
    prep_t3<<<In, 64>>>(tp, sw);
    sim_mma<<<dim3(22, Bn), 256, SMEM_TOTAL>>>(x, out);
}

// round 5
// speedup vs baseline: 4.3162x; 1.1882x over previous
#include <cuda_runtime.h>
#include <cuda_fp16.h>
#include <cstdint>

#define Bn 32
#define Cn 64
#define Hn 64
#define Wn 64
#define In 128
#define RT 4
#define WPAD 72
#define BROWS 432            // 6*72 input rows
#define BSTRIDE 272          // 64 half2 (256B) + 16B pad -> ldmatrix conflict-free
#define ASTRIDE 48           // 16 fp16 + 16B pad
#define ACHUNK (128 * ASTRIDE)   // 6144
#define ATAP (8 * ACHUNK)        // 49152
#define SM_A 0
#define SM_B (2 * ATAP)          // 98304
#define SMEM_TOTAL (SM_B + BROWS * BSTRIDE)  // 215808

__device__ __align__(16) unsigned char g_A[9 * ATAP];
__device__ float g_nt3[In];

// ---------------- prep ----------------
__global__ void prep_A(const float* __restrict__ tp, const float* __restrict__ sw) {
    int idx = blockIdx.x * 256 + threadIdx.x;
    if (idx >= 9 * 8 * 128 * 16) return;
    int e     = idx & 15;
    int row   = (idx >> 4) & 127;
    int chunk = (idx >> 11) & 7;
    int tap   = idx >> 14;
    int kk = chunk * 16 + e;
    int c = kk >> 1, s = kk & 1;
    int kh = tap / 3, kw = tap - kh * 3;
    int widx = ((row * Cn + c) * 3 + kh) * 3 + kw;
    float w = fabsf(sw[widx]);
    float t = tp[widx];
    float val = s ? -w : 2.0f * w * t;
    *(__half*)(g_A + (size_t)tap * ATAP + chunk * ACHUNK + row * ASTRIDE + e * 2) =
        __float2half_rn(val);
}

__global__ void prep_t3(const float* __restrict__ tp, const float* __restrict__ sw) {
    int i = blockIdx.x;
    int c = threadIdx.x;
    float s = 0.f;
    int base = (i * Cn + c) * 9;
#pragma unroll
    for (int tap = 0; tap < 9; tap++) {
        float w = fabsf(sw[base + tap]);
        float t = tp[base + tap];
        s += w * t * t;
    }
    __shared__ float red[64];
    red[c] = s;
    __syncthreads();
    for (int off = 32; off > 0; off >>= 1) {
        if (c < off) red[c] += red[c + off];
        __syncthreads();
    }
    if (c == 0) g_nt3[i] = -red[0];
}

// ---------------- helpers ----------------
__device__ __forceinline__ uint32_t smem_u32(const void* p) {
    uint32_t a;
    asm("{ .reg .u64 t; cvta.to.shared.u64 t, %1; cvt.u32.u64 %0, t; }" : "=r"(a) : "l"(p));
    return a;
}
__device__ __forceinline__ void cp16(uint32_t dst, const void* src) {
    asm volatile("cp.async.cg.shared.global [%0], [%1], 16;" :: "r"(dst), "l"(src) : "memory");
}
__device__ __forceinline__ void cp_commit() {
    asm volatile("cp.async.commit_group;" ::: "memory");
}
__device__ __forceinline__ void ldmx4(uint32_t* r, uint32_t addr) {
    asm volatile("ldmatrix.sync.aligned.m8n8.x4.shared.b16 {%0,%1,%2,%3}, [%4];"
                 : "=r"(r[0]), "=r"(r[1]), "=r"(r[2]), "=r"(r[3]) : "r"(addr));
}
__device__ __forceinline__ void mma16816(float* c, const uint32_t* a,
                                         const uint32_t b0, const uint32_t b1) {
    asm volatile(
        "mma.sync.aligned.m16n8k16.row.col.f32.f16.f16.f32 "
        "{%0,%1,%2,%3}, {%4,%5,%6,%7}, {%8,%9}, {%0,%1,%2,%3};"
        : "+f"(c[0]), "+f"(c[1]), "+f"(c[2]), "+f"(c[3])
        : "r"(a[0]), "r"(a[1]), "r"(a[2]), "r"(a[3]), "r"(b0), "r"(b1));
}

// ---------------- main: grid (16 row-tiles, 32 batches), 256 threads ----------------
__global__ void __launch_bounds__(256, 1) sim_mma(const float* __restrict__ x,
                                                  float* __restrict__ out) {
    extern __shared__ __align__(16) unsigned char smem[];
    const uint32_t sb = smem_u32(smem);
    const int tid  = threadIdx.x;
    const int lane = tid & 31;
    const int warp = tid >> 5;
    const int wm = warp & 1;    // instances [wm*64, wm*64+64)
    const int wn = warp >> 1;   // output row y0+wn, 64 positions
    const int b  = blockIdx.y;
    const int y0 = blockIdx.x * RT;

    // prefetch A tap 0 into buffer 0
    {
        uint32_t d = sb + SM_A;
        const unsigned char* s = g_A;
        for (int j = tid * 16; j < ATAP; j += 256 * 16) cp16(d + j, s + j);
        cp_commit();
    }

    // ---- B fill: row r = li*72+lx, 64 half2 (x, x^2); c fastest for STS coalescing ----
    const float* xb = x + (size_t)b * Cn * Hn * Wn;
    for (int idx = tid; idx < Cn * BROWS; idx += 256) {
        int c = idx & 63;
        int r = idx >> 6;
        int li = r / WPAD;
        int lx = r - li * WPAD;
        int gy = y0 + li - 1, gx = lx - 1;
        float v = 0.f;
        if ((unsigned)gy < Hn && (unsigned)gx < Wn) v = xb[(c * Hn + gy) * Wn + gx];
        __half2 h = __floats2half2_rn(v, v * v);
        *(uint32_t*)(smem + SM_B + r * BSTRIDE + c * 4) = *(uint32_t*)&h;
    }

    // ---- per-lane ldmatrix base addresses ----
    uint32_t arow[4];
#pragma unroll
    for (int t = 0; t < 4; t++)
        arow[t] = (uint32_t)((wm * 64 + t * 16 + (lane & 15)) * ASTRIDE) + ((lane >> 4) * 16);
    uint32_t bb[4];
#pragma unroll
    for (int j2 = 0; j2 < 4; j2++) {
        int xo = j2 * 16 + ((lane >> 4) & 1) * 8 + (lane & 7);
        bb[j2] = sb + SM_B + (uint32_t)((wn * WPAD + xo) * BSTRIDE) + ((lane >> 3) & 1) * 16;
    }

    float acc[4][8][4];
#pragma unroll
    for (int t = 0; t < 4; t++)
#pragma unroll
        for (int j = 0; j < 8; j++)
#pragma unroll
            for (int q = 0; q < 4; q++) acc[t][j][q] = 0.f;

    // ---- main loop: 9 taps, pipelined A prefetch ----
    for (int tap = 0; tap < 9; tap++) {
        if (tap < 8) {
            uint32_t d = sb + SM_A + ((tap + 1) & 1) * ATAP;
            const unsigned char* s = g_A + (size_t)(tap + 1) * ATAP;
            for (int j = tid * 16; j < ATAP; j += 256 * 16) cp16(d + j, s + j);
            cp_commit();
            asm volatile("cp.async.wait_group 1;" ::: "memory");
        } else {
            asm volatile("cp.async.wait_group 0;" ::: "memory");
        }
        __syncthreads();

        const int kh = tap / 3, kw = tap - kh * 3;
        const uint32_t tapoff = (uint32_t)((kh * WPAD + kw) * BSTRIDE);
        const uint32_t abuf = sb + SM_A + (tap & 1) * ATAP;

#pragma unroll
        for (int chunk = 0; chunk < 8; chunk++) {
            uint32_t a[4][4];
#pragma unroll
            for (int t = 0; t < 4; t++)
                ldmx4(a[t], abuf + chunk * ACHUNK + arow[t]);
            uint32_t br[4][4];
#pragma unroll
            for (int j2 = 0; j2 < 4; j2++)
                ldmx4(br[j2], bb[j2] + tapoff + chunk * 32);
#pragma unroll
            for (int t = 0; t < 4; t++)
#pragma unroll
                for (int j2 = 0; j2 < 4; j2++) {
                    mma16816(acc[t][2 * j2],     a[t], br[j2][0], br[j2][1]);
                    mma16816(acc[t][2 * j2 + 1], a[t], br[j2][2], br[j2][3]);
                }
        }
        __syncthreads();
    }

    // ---- epilogue: bias + store (warp wn owns output row y0+wn) ----
    const int gy = y0 + wn;
#pragma unroll
    for (int t = 0; t < 4; t++) {
        const int m_lo = wm * 64 + t * 16 + (lane >> 2);
        const int m_hi = m_lo + 8;
        const float bias_lo = g_nt3[m_lo];
        const float bias_hi = g_nt3[m_hi];
        float* o_lo = out + (((size_t)b * In + m_lo) * Hn + gy) * Wn;
        float* o_hi = out + (((size_t)b * In + m_hi) * Hn + gy) * Wn;
#pragma unroll
        for (int j = 0; j < 8; j++) {
            const int xc = j * 8 + 2 * (lane & 3);
            *(float2*)(o_lo + xc) = make_float2(acc[t][j][0] + bias_lo, acc[t][j][1] + bias_lo);
            *(float2*)(o_hi + xc) = make_float2(acc[t][j][2] + bias_hi, acc[t][j][3] + bias_hi);
        }
    }
}

extern "C" void kernel_launch(void* const* d_in, const int* in_sizes, int n_in,
                              void* d_out, int out_size) {
    const float* x  = (const float*)d_in[0];
    const float* tp = (const float*)d_in[1];
    const float* sw = (const float*)d_in[2];
    float* out = (float*)d_out;

    cudaFuncSetAttribute(sim_mma, cudaFuncAttributeMaxDynamicSharedMemorySize, SMEM_TOTAL);

    prep_A<<<(9 * 8 * 128 * 16 + 255) / 256, 256>>>(tp, sw);
    prep_t3<<<In, 64>>>(tp, sw);
    sim_mma<<<dim3(16, Bn), 256, SMEM_TOTAL>>>(x, out);
}